// round 3
// baseline (speedup 1.0000x reference)
#include <cuda_runtime.h>
#include <cuda_bf16.h>
#include <cstdint>
#include <cstddef>

#define NODES  100000
#define K1     256
#define C1     128
#define C2     16
#define NEDGES 1600000

// ---------------- scratch (device globals; no runtime allocation) ----------
__device__ unsigned g_deg[NODES];                     // integer degree
__device__ float g_dinv[NODES];                       // rsqrt(deg)
__device__ float g_Hs1[(size_t)NODES * C1];           // dinv*X@W1, later H1r
__device__ float g_agg1[(size_t)NODES * C1];          // edge-sum layer 1
__device__ float g_Hs2[(size_t)NODES * C2];           // dinv*H1r@W2
__device__ int   g_is64;                              // edge_index dtype flag

// ---------------- f32x2 packed-FMA helpers (Blackwell) ---------------------
__device__ __forceinline__ unsigned long long pack2(float x) {
    unsigned long long r;
    asm("mov.b64 %0, {%1, %1};" : "=l"(r) : "f"(x));
    return r;
}
__device__ __forceinline__ void fma2(unsigned long long& d,
                                     unsigned long long a,
                                     unsigned long long b) {
    asm("fma.rn.f32x2 %0, %1, %2, %0;" : "+l"(d) : "l"(a), "l"(b));
}
__device__ __forceinline__ float2 unpack2(unsigned long long v) {
    float2 r;
    asm("mov.b64 {%0, %1}, %2;" : "=f"(r.x), "=f"(r.y) : "l"(v));
    return r;
}

// ---------------- edge-index dtype detection & load -------------------------
// int32 data reinterpreted as int64 gives lo + hi*2^32; any nonzero hi word
// (probability 1 - 1e-80 over 16 samples of random node ids) lands outside
// [0, NODES), flagging 32-bit.
__global__ void k_detect(const long long* __restrict__ ei) {
    if (blockIdx.x == 0 && threadIdx.x == 0) {
        int ok64 = 1;
        #pragma unroll
        for (int i = 0; i < 16; i++) {
            long long v = ei[i];
            if (v < 0 || v >= NODES) ok64 = 0;
        }
        g_is64 = ok64;
    }
}
__device__ __forceinline__ int load_idx(const void* ei, long long pos) {
    if (g_is64) return (int)__ldg(&((const long long*)ei)[pos]);
    return __ldg(&((const int*)ei)[pos]);
}

// ---------------- init: deg=1 (self-loop) + zero agg1 ------------------------
__global__ void k_init() {
    size_t i = (size_t)blockIdx.x * blockDim.x + threadIdx.x;
    if (i < NODES) g_deg[i] = 1u;
    if (i < (size_t)NODES * (C1 / 4))
        *(float4*)&g_agg1[i * 4] = make_float4(0.f, 0.f, 0.f, 0.f);
}

__global__ void k_count(const void* __restrict__ ei) {
    int e = blockIdx.x * blockDim.x + threadIdx.x;
    if (e < NEDGES) {
        int d = load_idx(ei, (long long)NEDGES + e);
        asm volatile("red.global.add.u32 [%0], %1;"
                     :: "l"(&g_deg[d]), "r"(1u) : "memory");
    }
}
__global__ void k_rsqrt() {
    int i = blockIdx.x * blockDim.x + threadIdx.x;
    if (i < NODES) g_dinv[i] = rsqrtf((float)g_deg[i]);
}

__global__ void k_zero_out(float* __restrict__ out) {
    int i = blockIdx.x * blockDim.x + threadIdx.x;
    if (i < NODES * (C2 / 4))
        *(float4*)&out[i * 4] = make_float4(0.f, 0.f, 0.f, 0.f);
}

// ---------------- GEMM1: Hs1 = dinv * (X @ W1)  [100000x256 @ 256x128] ------
// 64x128 tile / block, k-tile 32, double-buffered smem.
__global__ __launch_bounds__(256) void k_gemm1(const float* __restrict__ X,
                                               const float* __restrict__ W1) {
    __shared__ float Xs[2][64][36];   // padded rows: 36 floats = 144B
    __shared__ float Ws[2][32][128];
    int tid = threadIdx.x;
    int ty = tid >> 4;               // 0..15
    int tx = tid & 15;               // 0..15
    int row0 = blockIdx.x * 64;

    unsigned long long acc[4][4];
    #pragma unroll
    for (int i = 0; i < 4; i++)
        #pragma unroll
        for (int j = 0; j < 4; j++) acc[i][j] = 0ull;

    // per-thread load coords
    int xr[2], xk[2];
    #pragma unroll
    for (int p = 0; p < 2; p++) {
        int t4 = tid + 256 * p;          // 0..511
        xr[p] = t4 >> 3;                 // 0..63
        xk[p] = (t4 & 7) * 4;            // 0,4,...,28
    }
    int wk[4], wc[4];
    #pragma unroll
    for (int p = 0; p < 4; p++) {
        int t4 = tid + 256 * p;          // 0..1023
        wk[p] = t4 >> 5;                 // 0..31
        wc[p] = (t4 & 31) * 4;           // 0..124
    }

    float4 xv[2], wv4[4];
    // prologue: load tile 0
    #pragma unroll
    for (int p = 0; p < 2; p++) {
        int row = row0 + xr[p];
        xv[p] = make_float4(0.f, 0.f, 0.f, 0.f);
        if (row < NODES)
            xv[p] = *(const float4*)&X[(size_t)row * K1 + xk[p]];
    }
    #pragma unroll
    for (int p = 0; p < 4; p++)
        wv4[p] = *(const float4*)&W1[(size_t)wk[p] * C1 + wc[p]];
    #pragma unroll
    for (int p = 0; p < 2; p++) *(float4*)&Xs[0][xr[p]][xk[p]] = xv[p];
    #pragma unroll
    for (int p = 0; p < 4; p++) *(float4*)&Ws[0][wk[p]][wc[p]] = wv4[p];
    __syncthreads();

    #pragma unroll 1
    for (int kk = 0; kk < K1 / 32; kk++) {
        int cur = kk & 1, nxt = cur ^ 1;
        // prefetch next tile (global -> regs) before compute
        if (kk + 1 < K1 / 32) {
            int kbase = (kk + 1) * 32;
            #pragma unroll
            for (int p = 0; p < 2; p++) {
                int row = row0 + xr[p];
                xv[p] = make_float4(0.f, 0.f, 0.f, 0.f);
                if (row < NODES)
                    xv[p] = *(const float4*)&X[(size_t)row * K1 + kbase + xk[p]];
            }
            #pragma unroll
            for (int p = 0; p < 4; p++)
                wv4[p] = *(const float4*)&W1[(size_t)(kbase + wk[p]) * C1 + wc[p]];
        }
        // compute on current buffer
        #pragma unroll
        for (int k = 0; k < 32; k++) {
            unsigned long long xa[4];
            #pragma unroll
            for (int i = 0; i < 4; i++) xa[i] = pack2(Xs[cur][ty + 16 * i][k]);
            unsigned long long wv[4];
            #pragma unroll
            for (int j = 0; j < 4; j++)
                wv[j] = *(unsigned long long*)&Ws[cur][k][2 * tx + 32 * j];
            #pragma unroll
            for (int i = 0; i < 4; i++)
                #pragma unroll
                for (int j = 0; j < 4; j++) fma2(acc[i][j], xa[i], wv[j]);
        }
        // commit prefetch to next buffer
        if (kk + 1 < K1 / 32) {
            #pragma unroll
            for (int p = 0; p < 2; p++) *(float4*)&Xs[nxt][xr[p]][xk[p]] = xv[p];
            #pragma unroll
            for (int p = 0; p < 4; p++) *(float4*)&Ws[nxt][wk[p]][wc[p]] = wv4[p];
            __syncthreads();
        }
    }
    // epilogue: scale by dinv[row]
    #pragma unroll
    for (int i = 0; i < 4; i++) {
        int row = row0 + ty + 16 * i;
        if (row >= NODES) continue;
        float dv = g_dinv[row];
        #pragma unroll
        for (int j = 0; j < 4; j++) {
            float2 v = unpack2(acc[i][j]);
            v.x *= dv; v.y *= dv;
            *(float2*)&g_Hs1[(size_t)row * C1 + 2 * tx + 32 * j] = v;
        }
    }
}

// ---------------- scatter layer 1: agg1[d] += Hs1[s], 1 warp/edge -----------
__global__ __launch_bounds__(256) void k_scatter1(const void* __restrict__ ei) {
    long long w = ((long long)blockIdx.x * blockDim.x + threadIdx.x) >> 5;
    int lane = threadIdx.x & 31;
    if (w >= NEDGES) return;
    int s = load_idx(ei, w);
    int d = load_idx(ei, (long long)NEDGES + w);
    float4 v = *(const float4*)&g_Hs1[(size_t)s * C1 + lane * 4];
    float* p = &g_agg1[(size_t)d * C1 + lane * 4];
    asm volatile("red.global.add.v4.f32 [%0], {%1, %2, %3, %4};"
                 :: "l"(p), "f"(v.x), "f"(v.y), "f"(v.z), "f"(v.w) : "memory");
}

// ---------------- epilogue 1: H1r = relu(dinv*(agg1+Hs1)+b1) into Hs1 -------
__global__ void k_epi1(const float* __restrict__ b1) {
    size_t i4 = (size_t)blockIdx.x * blockDim.x + threadIdx.x;
    if (i4 >= (size_t)NODES * (C1 / 4)) return;
    int row = (int)(i4 >> 5);
    int c = ((int)i4 & 31) * 4;
    float dv = g_dinv[row];
    float4 a = *(float4*)&g_agg1[i4 * 4];
    float4 h = *(float4*)&g_Hs1[i4 * 4];
    float4 b = *(const float4*)&b1[c];
    float4 o;
    o.x = fmaxf(dv * (a.x + h.x) + b.x, 0.f);
    o.y = fmaxf(dv * (a.y + h.y) + b.y, 0.f);
    o.z = fmaxf(dv * (a.z + h.z) + b.z, 0.f);
    o.w = fmaxf(dv * (a.w + h.w) + b.w, 0.f);
    *(float4*)&g_Hs1[i4 * 4] = o;
}

// ---------------- GEMM2: Hs2 = dinv * (H1r @ W2)  [100000x128 @ 128x16] -----
__global__ __launch_bounds__(256) void k_gemm2(const float* __restrict__ W2) {
    __shared__ float Hs[64][132];     // 132 floats = 528B (16B multiple)
    __shared__ float Ws2[C1][C2];
    int tid = threadIdx.x;
    int row0 = blockIdx.x * 64;
    #pragma unroll
    for (int p = 0; p < 2; p++) {
        int t4 = tid + 256 * p;
        *(float4*)&((float*)Ws2)[t4 * 4] = *(const float4*)&W2[t4 * 4];
    }
    #pragma unroll
    for (int p = 0; p < 8; p++) {
        int t4 = tid + 256 * p;          // 0..2047
        int r  = t4 >> 5;
        int c4 = t4 & 31;
        int row = row0 + r;
        float4 v = make_float4(0.f, 0.f, 0.f, 0.f);
        if (row < NODES) v = *(const float4*)&g_Hs1[(size_t)row * C1 + c4 * 4];
        *(float4*)&Hs[r][c4 * 4] = v;
    }
    __syncthreads();
    int r = tid >> 2;       // row within tile
    int q = tid & 3;        // 4-col group
    unsigned long long a0 = 0ull, a1 = 0ull;
    #pragma unroll
    for (int k = 0; k < C1; k++) {
        unsigned long long x  = pack2(Hs[r][k]);
        unsigned long long w0 = *(unsigned long long*)&Ws2[k][q * 4];
        unsigned long long w1 = *(unsigned long long*)&Ws2[k][q * 4 + 2];
        fma2(a0, x, w0);
        fma2(a1, x, w1);
    }
    int row = row0 + r;
    if (row < NODES) {
        float dv = g_dinv[row];
        float2 v0 = unpack2(a0), v1 = unpack2(a1);
        float4 o = make_float4(v0.x * dv, v0.y * dv, v1.x * dv, v1.y * dv);
        *(float4*)&g_Hs2[(size_t)row * C2 + q * 4] = o;
    }
}

// ---------------- scatter layer 2: out[d] += Hs2[s], 4 lanes/edge -----------
__global__ __launch_bounds__(256) void k_scatter2(const void* __restrict__ ei,
                                                  float* __restrict__ out) {
    long long idx = (long long)blockIdx.x * blockDim.x + threadIdx.x;
    long long e = idx >> 2;
    int q = (int)idx & 3;
    if (e >= NEDGES) return;
    int s = load_idx(ei, e);
    int d = load_idx(ei, (long long)NEDGES + e);
    float4 v = *(const float4*)&g_Hs2[(size_t)s * C2 + q * 4];
    float* p = &out[(size_t)d * C2 + q * 4];
    asm volatile("red.global.add.v4.f32 [%0], {%1, %2, %3, %4};"
                 :: "l"(p), "f"(v.x), "f"(v.y), "f"(v.z), "f"(v.w) : "memory");
}

// ---------------- epilogue 2: out = dinv*(out+Hs2)+b2 (in place) ------------
__global__ void k_epi2(const float* __restrict__ b2, float* __restrict__ out) {
    int i4 = blockIdx.x * blockDim.x + threadIdx.x;
    if (i4 >= NODES * (C2 / 4)) return;
    int row = i4 >> 2;
    int c = (i4 & 3) * 4;
    float dv = g_dinv[row];
    float4 s = *(float4*)&out[(size_t)i4 * 4];
    float4 h = *(float4*)&g_Hs2[(size_t)i4 * 4];
    float4 b = *(const float4*)&b2[c];
    float4 o = make_float4(dv * (s.x + h.x) + b.x,
                           dv * (s.y + h.y) + b.y,
                           dv * (s.z + h.z) + b.z,
                           dv * (s.w + h.w) + b.w);
    *(float4*)&out[(size_t)i4 * 4] = o;
}

// ---------------- launch -----------------------------------------------------
extern "C" void kernel_launch(void* const* d_in, const int* in_sizes, int n_in,
                              void* d_out, int out_size) {
    const float* X  = (const float*)d_in[0];
    const void*  EI = d_in[1];                 // int64 or int32, detected
    const float* W1 = (const float*)d_in[2];
    const float* b1 = (const float*)d_in[3];
    const float* W2 = (const float*)d_in[4];
    const float* b2 = (const float*)d_in[5];
    float* out = (float*)d_out;

    k_detect<<<1, 32>>>((const long long*)EI);

    // degree / dinv (+ zero agg1 in the same pass)
    k_init<<<(NODES * (C1 / 4) + 255) / 256, 256>>>();
    k_count<<<(NEDGES + 255) / 256, 256>>>(EI);
    k_rsqrt<<<(NODES + 255) / 256, 256>>>();

    // layer 1
    k_gemm1<<<(NODES + 63) / 64, 256>>>(X, W1);
    {
        long long threads = (long long)NEDGES * 32;
        k_scatter1<<<(unsigned)((threads + 255) / 256), 256>>>(EI);
    }
    k_epi1<<<(NODES * (C1 / 4) + 255) / 256, 256>>>(b1);

    // layer 2
    k_gemm2<<<(NODES + 63) / 64, 256>>>(W2);
    k_zero_out<<<(NODES * (C2 / 4) + 255) / 256, 256>>>(out);
    {
        long long threads = (long long)NEDGES * 4;
        k_scatter2<<<(unsigned)((threads + 255) / 256), 256>>>(EI, out);
    }
    k_epi2<<<(NODES * (C2 / 4) + 255) / 256, 256>>>(b2, out);
}

// round 15
// speedup vs baseline: 1.6774x; 1.6774x over previous
#include <cuda_runtime.h>
#include <cuda_bf16.h>
#include <cstdint>
#include <cstddef>

#define NODES  100000
#define K1     256
#define C1     128
#define C2     16
#define NEDGES 1600000

// ---------------- scratch (device globals; no runtime allocation) ----------
__device__ unsigned g_deg[NODES];
__device__ float g_dinv[NODES];
__device__ float g_Hs1[(size_t)NODES * C1];           // dinv*X@W1, later H1r
__device__ float g_agg1[(size_t)NODES * C1];          // edge-sum layer 1
__device__ float g_Hs2[(size_t)NODES * C2];           // dinv*H1r@W2
__device__ int   g_is64;
// W1 pre-transposed to [n=128][k=256] bf16 hi/lo split
__device__ __nv_bfloat16 g_W1h[C1 * K1];
__device__ __nv_bfloat16 g_W1l[C1 * K1];

// ---------------- f32x2 packed-FMA helpers (for GEMM2) ----------------------
__device__ __forceinline__ unsigned long long pack2(float x) {
    unsigned long long r;
    asm("mov.b64 %0, {%1, %1};" : "=l"(r) : "f"(x));
    return r;
}
__device__ __forceinline__ void fma2(unsigned long long& d,
                                     unsigned long long a,
                                     unsigned long long b) {
    asm("fma.rn.f32x2 %0, %1, %2, %0;" : "+l"(d) : "l"(a), "l"(b));
}
__device__ __forceinline__ float2 unpack2(unsigned long long v) {
    float2 r;
    asm("mov.b64 {%0, %1}, %2;" : "=f"(r.x), "=f"(r.y) : "l"(v));
    return r;
}

// ---------------- mma.sync helper -------------------------------------------
__device__ __forceinline__ void mma_bf16(float* d, const uint32_t* a,
                                         uint32_t b0, uint32_t b1) {
    asm volatile(
        "mma.sync.aligned.m16n8k16.row.col.f32.bf16.bf16.f32 "
        "{%0,%1,%2,%3}, {%4,%5,%6,%7}, {%8,%9}, {%0,%1,%2,%3};"
        : "+f"(d[0]), "+f"(d[1]), "+f"(d[2]), "+f"(d[3])
        : "r"(a[0]), "r"(a[1]), "r"(a[2]), "r"(a[3]), "r"(b0), "r"(b1));
}
__device__ __forceinline__ uint32_t bf2pack(float x, float y) {
    __nv_bfloat162 t(__float2bfloat16_rn(x), __float2bfloat16_rn(y));
    return *(uint32_t*)&t;
}

// ---------------- edge-index dtype detection & load -------------------------
// int32 data reinterpreted as int64 gives lo + hi*2^32; nonzero hi words land
// outside [0, NODES), flagging 32-bit.
__global__ void k_detect(const long long* __restrict__ ei) {
    if (blockIdx.x == 0 && threadIdx.x == 0) {
        int ok64 = 1;
        #pragma unroll
        for (int i = 0; i < 16; i++) {
            long long v = ei[i];
            if (v < 0 || v >= NODES) ok64 = 0;
        }
        g_is64 = ok64;
    }
}
__device__ __forceinline__ int load_idx(const void* ei, long long pos) {
    if (g_is64) return (int)__ldg(&((const long long*)ei)[pos]);
    return __ldg(&((const int*)ei)[pos]);
}

// ---------------- W1 split prep: [n][k] bf16 hi/lo ---------------------------
__global__ void k_prepW(const float* __restrict__ W1) {
    int i = blockIdx.x * blockDim.x + threadIdx.x;   // i = n*256 + k
    if (i < C1 * K1) {
        int n = i >> 8, k = i & 255;
        float v = W1[(size_t)k * C1 + n];
        __nv_bfloat16 h = __float2bfloat16_rn(v);
        g_W1h[i] = h;
        g_W1l[i] = __float2bfloat16_rn(v - __bfloat162float(h));
    }
}

// ---------------- init: deg=1 (self-loop) + zero agg1 ------------------------
__global__ void k_init() {
    size_t i = (size_t)blockIdx.x * blockDim.x + threadIdx.x;
    if (i < NODES) g_deg[i] = 1u;
    if (i < (size_t)NODES * (C1 / 4))
        *(float4*)&g_agg1[i * 4] = make_float4(0.f, 0.f, 0.f, 0.f);
}
__global__ void k_count(const void* __restrict__ ei) {
    int e = blockIdx.x * blockDim.x + threadIdx.x;
    if (e < NEDGES) {
        int d = load_idx(ei, (long long)NEDGES + e);
        asm volatile("red.global.add.u32 [%0], %1;"
                     :: "l"(&g_deg[d]), "r"(1u) : "memory");
    }
}
__global__ void k_rsqrt() {
    int i = blockIdx.x * blockDim.x + threadIdx.x;
    if (i < NODES) g_dinv[i] = rsqrtf((float)g_deg[i]);
}
__global__ void k_zero_out(float* __restrict__ out) {
    int i = blockIdx.x * blockDim.x + threadIdx.x;
    if (i < NODES * (C2 / 4))
        *(float4*)&out[i * 4] = make_float4(0.f, 0.f, 0.f, 0.f);
}

// ---------------- GEMM1 (mma.sync bf16 split): Hs1 = dinv * (X @ W1) --------
// CTA: 128 rows x 128 cols, 8 warps (warp w -> rows w*16..w*16+15, all cols).
// K chunks of 32; 4 static smem tiles of [128][32] bf16 at 80B pitch
// (bank = (g*20+tig) mod 32 across fragment lanes -> conflict-free).
// D = Xh*Wh + Xh*Wl + Xl*Wh, fp32 accum (XlWl dropped, ~2^-16 rel).
#define PB 80
#define XH_OFF 0
#define XL_OFF 10240
#define WH_OFF 20480
#define WL_OFF 30720
#define SMTOT  40960

__global__ __launch_bounds__(256) void k_gemm1_mma(const float* __restrict__ X) {
    __shared__ char sm[SMTOT];
    int tid = threadIdx.x;
    int w = tid >> 5, lane = tid & 31;
    int g = lane >> 2, tig = lane & 3;
    int row0 = blockIdx.x * 128;

    float d[16][4];
    #pragma unroll
    for (int j = 0; j < 16; j++)
        #pragma unroll
        for (int q = 0; q < 4; q++) d[j][q] = 0.f;

    int srow = tid >> 1;                    // 0..127 (stage row / W n-index)
    int sh   = tid & 1;                     // half of the 32-k chunk
    bool svalid = (row0 + srow) < NODES;
    const float4* xsrc = (const float4*)&X[(size_t)(svalid ? row0 + srow : 0) * K1];

    #pragma unroll 1
    for (int c = 0; c < 8; c++) {
        if (c > 0) __syncthreads();
        // ---- stage X chunk: 32 fp32 -> bf16 hi/lo ----
        {
            char* xh = sm + XH_OFF + srow * PB + sh * 32;
            char* xl = sm + XL_OFF + srow * PB + sh * 32;
            #pragma unroll
            for (int i = 0; i < 4; i++) {
                float4 v = make_float4(0.f, 0.f, 0.f, 0.f);
                if (svalid) v = xsrc[c * 8 + sh * 4 + i];
                uint32_t h0 = bf2pack(v.x, v.y), h1 = bf2pack(v.z, v.w);
                float2 r0 = make_float2(v.x - __bfloat162float(__float2bfloat16_rn(v.x)),
                                        v.y - __bfloat162float(__float2bfloat16_rn(v.y)));
                float2 r1 = make_float2(v.z - __bfloat162float(__float2bfloat16_rn(v.z)),
                                        v.w - __bfloat162float(__float2bfloat16_rn(v.w)));
                uint32_t l0 = bf2pack(r0.x, r0.y), l1 = bf2pack(r1.x, r1.y);
                *(uint2*)(xh + i * 8) = make_uint2(h0, h1);
                *(uint2*)(xl + i * 8) = make_uint2(l0, l1);
            }
        }
        // ---- stage W chunk: [n][k] bf16, straight copy ----
        {
            const uint4* wh = (const uint4*)&g_W1h[srow * K1 + c * 32 + sh * 16];
            const uint4* wl = (const uint4*)&g_W1l[srow * K1 + c * 32 + sh * 16];
            char* dh = sm + WH_OFF + srow * PB + sh * 32;
            char* dl = sm + WL_OFF + srow * PB + sh * 32;
            #pragma unroll
            for (int i = 0; i < 2; i++) {
                *(uint4*)(dh + i * 16) = wh[i];
                *(uint4*)(dl + i * 16) = wl[i];
            }
        }
        __syncthreads();
        // ---- compute: 2 k16 steps ----
        #pragma unroll
        for (int s = 0; s < 2; s++) {
            int kb = s * 16;
            int abase = (w * 16 + g) * PB + (kb + 2 * tig) * 2;
            uint32_t ah[4], al[4];
            ah[0] = *(uint32_t*)(sm + XH_OFF + abase);
            ah[2] = *(uint32_t*)(sm + XH_OFF + abase + 16);
            ah[1] = *(uint32_t*)(sm + XH_OFF + abase + 8 * PB);
            ah[3] = *(uint32_t*)(sm + XH_OFF + abase + 8 * PB + 16);
            al[0] = *(uint32_t*)(sm + XL_OFF + abase);
            al[2] = *(uint32_t*)(sm + XL_OFF + abase + 16);
            al[1] = *(uint32_t*)(sm + XL_OFF + abase + 8 * PB);
            al[3] = *(uint32_t*)(sm + XL_OFF + abase + 8 * PB + 16);
            #pragma unroll
            for (int j = 0; j < 16; j++) {
                int bbase = (j * 8 + g) * PB + (kb + 2 * tig) * 2;
                uint32_t bh0 = *(uint32_t*)(sm + WH_OFF + bbase);
                uint32_t bh1 = *(uint32_t*)(sm + WH_OFF + bbase + 16);
                uint32_t bl0 = *(uint32_t*)(sm + WL_OFF + bbase);
                uint32_t bl1 = *(uint32_t*)(sm + WL_OFF + bbase + 16);
                mma_bf16(d[j], ah, bh0, bh1);
                mma_bf16(d[j], ah, bl0, bl1);
                mma_bf16(d[j], al, bh0, bh1);
            }
        }
    }
    // ---- epilogue: scale by dinv, store ----
    int r0 = row0 + w * 16 + g;
    int r1 = r0 + 8;
    float dv0 = (r0 < NODES) ? g_dinv[r0] : 0.f;
    float dv1 = (r1 < NODES) ? g_dinv[r1] : 0.f;
    #pragma unroll
    for (int j = 0; j < 16; j++) {
        int col = j * 8 + 2 * tig;
        if (r0 < NODES)
            *(float2*)&g_Hs1[(size_t)r0 * C1 + col] =
                make_float2(d[j][0] * dv0, d[j][1] * dv0);
        if (r1 < NODES)
            *(float2*)&g_Hs1[(size_t)r1 * C1 + col] =
                make_float2(d[j][2] * dv1, d[j][3] * dv1);
    }
}

// ---------------- scatter layer 1: agg1[d] += Hs1[s], 1 warp/edge -----------
__global__ __launch_bounds__(256) void k_scatter1(const void* __restrict__ ei) {
    long long w = ((long long)blockIdx.x * blockDim.x + threadIdx.x) >> 5;
    int lane = threadIdx.x & 31;
    if (w >= NEDGES) return;
    int s = load_idx(ei, w);
    int d = load_idx(ei, (long long)NEDGES + w);
    float4 v = *(const float4*)&g_Hs1[(size_t)s * C1 + lane * 4];
    float* p = &g_agg1[(size_t)d * C1 + lane * 4];
    asm volatile("red.global.add.v4.f32 [%0], {%1, %2, %3, %4};"
                 :: "l"(p), "f"(v.x), "f"(v.y), "f"(v.z), "f"(v.w) : "memory");
}

// ---------------- epilogue 1: H1r = relu(dinv*(agg1+Hs1)+b1) into Hs1 -------
__global__ void k_epi1(const float* __restrict__ b1) {
    size_t i4 = (size_t)blockIdx.x * blockDim.x + threadIdx.x;
    if (i4 >= (size_t)NODES * (C1 / 4)) return;
    int row = (int)(i4 >> 5);
    int c = ((int)i4 & 31) * 4;
    float dv = g_dinv[row];
    float4 a = *(float4*)&g_agg1[i4 * 4];
    float4 h = *(float4*)&g_Hs1[i4 * 4];
    float4 b = *(const float4*)&b1[c];
    float4 o;
    o.x = fmaxf(dv * (a.x + h.x) + b.x, 0.f);
    o.y = fmaxf(dv * (a.y + h.y) + b.y, 0.f);
    o.z = fmaxf(dv * (a.z + h.z) + b.z, 0.f);
    o.w = fmaxf(dv * (a.w + h.w) + b.w, 0.f);
    *(float4*)&g_Hs1[i4 * 4] = o;
}

// ---------------- GEMM2: Hs2 = dinv * (H1r @ W2)  [100000x128 @ 128x16] -----
__global__ __launch_bounds__(256) void k_gemm2(const float* __restrict__ W2) {
    __shared__ float Hs[64][132];
    __shared__ float Ws2[C1][C2];
    int tid = threadIdx.x;
    int row0 = blockIdx.x * 64;
    #pragma unroll
    for (int p = 0; p < 2; p++) {
        int t4 = tid + 256 * p;
        *(float4*)&((float*)Ws2)[t4 * 4] = *(const float4*)&W2[t4 * 4];
    }
    #pragma unroll
    for (int p = 0; p < 8; p++) {
        int t4 = tid + 256 * p;
        int r  = t4 >> 5;
        int c4 = t4 & 31;
        int row = row0 + r;
        float4 v = make_float4(0.f, 0.f, 0.f, 0.f);
        if (row < NODES) v = *(const float4*)&g_Hs1[(size_t)row * C1 + c4 * 4];
        *(float4*)&Hs[r][c4 * 4] = v;
    }
    __syncthreads();
    int r = tid >> 2;
    int q = tid & 3;
    unsigned long long a0 = 0ull, a1 = 0ull;
    #pragma unroll
    for (int k = 0; k < C1; k++) {
        unsigned long long x  = pack2(Hs[r][k]);
        unsigned long long w0 = *(unsigned long long*)&Ws2[k][q * 4];
        unsigned long long w1 = *(unsigned long long*)&Ws2[k][q * 4 + 2];
        fma2(a0, x, w0);
        fma2(a1, x, w1);
    }
    int row = row0 + r;
    if (row < NODES) {
        float dv = g_dinv[row];
        float2 v0 = unpack2(a0), v1 = unpack2(a1);
        float4 o = make_float4(v0.x * dv, v0.y * dv, v1.x * dv, v1.y * dv);
        *(float4*)&g_Hs2[(size_t)row * C2 + q * 4] = o;
    }
}

// ---------------- scatter layer 2: out[d] += Hs2[s], 4 lanes/edge -----------
__global__ __launch_bounds__(256) void k_scatter2(const void* __restrict__ ei,
                                                  float* __restrict__ out) {
    long long idx = (long long)blockIdx.x * blockDim.x + threadIdx.x;
    long long e = idx >> 2;
    int q = (int)idx & 3;
    if (e >= NEDGES) return;
    int s = load_idx(ei, e);
    int d = load_idx(ei, (long long)NEDGES + e);
    float4 v = *(const float4*)&g_Hs2[(size_t)s * C2 + q * 4];
    float* p = &out[(size_t)d * C2 + q * 4];
    asm volatile("red.global.add.v4.f32 [%0], {%1, %2, %3, %4};"
                 :: "l"(p), "f"(v.x), "f"(v.y), "f"(v.z), "f"(v.w) : "memory");
}

// ---------------- epilogue 2: out = dinv*(out+Hs2)+b2 (in place) ------------
__global__ void k_epi2(const float* __restrict__ b2, float* __restrict__ out) {
    int i4 = blockIdx.x * blockDim.x + threadIdx.x;
    if (i4 >= NODES * (C2 / 4)) return;
    int row = i4 >> 2;
    int c = (i4 & 3) * 4;
    float dv = g_dinv[row];
    float4 s = *(float4*)&out[(size_t)i4 * 4];
    float4 h = *(float4*)&g_Hs2[(size_t)i4 * 4];
    float4 b = *(const float4*)&b2[c];
    float4 o = make_float4(dv * (s.x + h.x) + b.x,
                           dv * (s.y + h.y) + b.y,
                           dv * (s.z + h.z) + b.z,
                           dv * (s.w + h.w) + b.w);
    *(float4*)&out[(size_t)i4 * 4] = o;
}

// ---------------- launch: kernel launches ONLY (graph-capturable) -----------
extern "C" void kernel_launch(void* const* d_in, const int* in_sizes, int n_in,
                              void* d_out, int out_size) {
    const float* X  = (const float*)d_in[0];
    const void*  EI = d_in[1];
    const float* W1 = (const float*)d_in[2];
    const float* b1 = (const float*)d_in[3];
    const float* W2 = (const float*)d_in[4];
    const float* b2 = (const float*)d_in[5];
    float* out = (float*)d_out;

    k_detect<<<1, 32>>>((const long long*)EI);
    k_prepW<<<(C1 * K1 + 255) / 256, 256>>>(W1);

    k_init<<<(NODES * (C1 / 4) + 255) / 256, 256>>>();
    k_count<<<(NEDGES + 255) / 256, 256>>>(EI);
    k_rsqrt<<<(NODES + 255) / 256, 256>>>();

    // layer 1
    k_gemm1_mma<<<(NODES + 127) / 128, 256>>>(X);
    {
        long long threads = (long long)NEDGES * 32;
        k_scatter1<<<(unsigned)((threads + 255) / 256), 256>>>(EI);
    }
    k_epi1<<<(NODES * (C1 / 4) + 255) / 256, 256>>>(b1);

    // layer 2
    k_gemm2<<<(NODES + 63) / 64, 256>>>(W2);
    k_zero_out<<<(NODES * (C2 / 4) + 255) / 256, 256>>>(out);
    {
        long long threads = (long long)NEDGES * 4;
        k_scatter2<<<(unsigned)((threads + 255) / 256), 256>>>(EI, out);
    }
    k_epi2<<<(NODES * (C2 / 4) + 255) / 256, 256>>>(b2, out);
}